// round 12
// baseline (speedup 1.0000x reference)
#include <cuda_runtime.h>
#include <math.h>

#define FULL 0xffffffffu
#define INVS10 0.31622776601683794f   // 1/sqrt(10)
#define EPS_ 1e-4f

typedef unsigned long long ull;

__device__ __forceinline__ ull PK(float lo, float hi) {
    ull r; asm("mov.b64 %0, {%1,%2};" : "=l"(r) : "f"(lo), "f"(hi)); return r;
}
__device__ __forceinline__ void UPK(ull v, float& lo, float& hi) {
    asm("mov.b64 {%0,%1}, %2;" : "=f"(lo), "=f"(hi) : "l"(v));
}
__device__ __forceinline__ ull FMA2(ull a, ull b, ull c) {
    ull d; asm("fma.rn.f32x2 %0, %1, %2, %3;" : "=l"(d) : "l"(a), "l"(b), "l"(c)); return d;
}
__device__ __forceinline__ ull MUL2(ull a, ull b) {
    ull d; asm("mul.rn.f32x2 %0, %1, %2;" : "=l"(d) : "l"(a), "l"(b)); return d;
}

// One struct per batch; one QUARTER-warp (8 lanes) owns one batch in all phases.
// Batch stride keeps the 4 simultaneous per-batch LDS broadcasts in distinct banks.
struct __align__(16) BatchSmem {
    float2 Lm[136];          // packed multiplier triangle; diag = (rsd,rsd)
    float2 Hy[16][10];       // staging: H cols 0..7, y col 8
    float2 pad[2];
};

__global__ __launch_bounds__(128, 5)
void mmse_pic_kernel(const float* __restrict__ y_re, const float* __restrict__ y_im,
                     const float* __restrict__ h_re, const float* __restrict__ h_im,
                     const float* __restrict__ prior,
                     const float* __restrict__ s_re, const float* __restrict__ s_im,
                     float* __restrict__ out, int nbatch)
{
    const int warp = threadIdx.x >> 5;
    const int lane = threadIdx.x & 31;
    const int qid  = lane >> 3;        // batch within warp (0..3)
    const int ql   = lane & 7;         // lane within batch
    const int base = blockIdx.x * 16 + warp * 4;

    __shared__ BatchSmem sm[16];
    BatchSmem* SB = &sm[warp * 4];     // this warp's 4 batches
    BatchSmem& Q = SB[qid];

    int b = base + qid; if (b >= nbatch) b = nbatch - 1;

    // ---------------- stage H and y (coalesced) for all 4 batches ----------------
    #pragma unroll
    for (int s2 = 0; s2 < 4; s2++) {
        int bg = base + s2; if (bg >= nbatch) bg = nbatch - 1;
        const float2* hre2 = (const float2*)(h_re + (size_t)bg * 128);
        const float2* him2 = (const float2*)(h_im + (size_t)bg * 128);
        #pragma unroll
        for (int t = lane; t < 64; t += 32) {
            int row = t >> 2, cp = t & 3;
            float2 re = hre2[t], im = him2[t];
            *(float4*)&SB[s2].Hy[row][cp * 2] = make_float4(re.x, im.x, re.y, im.y);
        }
        if (lane < 16)
            SB[s2].Hy[lane][8] = make_float2(y_re[(size_t)bg * 16 + lane],
                                             y_im[(size_t)bg * 16 + lane]);
    }
    __syncwarp();

    // ---------------- load 2 S columns per lane direct from global --------------
    // S Hermitian: column j == conj(row j); rows are contiguous float4 runs.
    ull vS[2][16];
    {
        const float4* sre4 = (const float4*)(s_re + (size_t)b * 256);
        const float4* sim4 = (const float4*)(s_im + (size_t)b * 256);
        #pragma unroll
        for (int c = 0; c < 2; c++) {
            int row = 2 * ql + c;
            #pragma unroll
            for (int q4 = 0; q4 < 4; q4++) {
                float4 r  = sre4[row * 4 + q4];
                float4 i4 = sim4[row * 4 + q4];
                vS[c][4 * q4 + 0] = PK(r.x, -i4.x);
                vS[c][4 * q4 + 1] = PK(r.y, -i4.y);
                vS[c][4 * q4 + 2] = PK(r.z, -i4.z);
                vS[c][4 * q4 + 3] = PK(r.w, -i4.w);
            }
        }
    }

    // ---------------- phase 1: LDL^H elimination of S (8 lanes per batch) -------
    float rsd0 = 0.f, rsd1 = 0.f, invd0 = 0.f, invd1 = 0.f;
    #pragma unroll
    for (int k = 0; k < 16; k++) {
        const int owner = k >> 1, cset = k & 1;
        float pr, pi_; UPK(vS[cset][k], pr, pi_);
        float dk = __shfl_sync(FULL, pr, owner, 8);
        float rsd = rsqrtf(dk);
        float invd = rsd * rsd;
        if (2 * ql == k)     { rsd0 = rsd; invd0 = invd; }
        if (2 * ql + 1 == k) { rsd1 = rsd; invd1 = invd; }
        bool up0 = (2 * ql) > k, up1 = (2 * ql + 1) > k;
        ull nim = PK(-invd, -invd);
        ull w0 = up0 ? MUL2(vS[0][k], nim) : 0ull;      // -invd * A[k][j0]
        ull w1 = up1 ? MUL2(vS[1][k], nim) : 0ull;
        float w0r, w0i; UPK(w0, w0r, w0i); ull w0b = PK(-w0i, w0r);
        float w1r, w1i; UPK(w1, w1r, w1i); ull w1b = PK(-w1i, w1r);
        #pragma unroll
        for (int i = k + 1; i < 16; i++) {
            float xr, xi; UPK(vS[cset][i], xr, xi);
            float mr = __shfl_sync(FULL, xr, owner, 8);   // A[i][k] raw
            float mi = __shfl_sync(FULL, xi, owner, 8);
            ull mr2 = PK(mr, mr), mi2 = PK(mi, mi);
            vS[0][i] = FMA2(mr2, w0, vS[0][i]);
            vS[0][i] = FMA2(mi2, w0b, vS[0][i]);
            vS[1][i] = FMA2(mr2, w1, vS[1][i]);
            vS[1][i] = FMA2(mi2, w1b, vS[1][i]);
        }
    }
    // store scaled multiplier columns (packed triangle) + diag rsd
    {
        int j0 = 2 * ql, j1 = 2 * ql + 1;
        int jb0 = j0 * (33 - j0) / 2, jb1 = j1 * (33 - j1) / 2;
        *(ull*)&Q.Lm[jb0] = PK(rsd0, rsd0);
        *(ull*)&Q.Lm[jb1] = PK(rsd1, rsd1);
        ull iv0 = PK(invd0, invd0), iv1 = PK(invd1, invd1);
        #pragma unroll
        for (int i = 1; i < 16; i++) {
            if (i > j0) *(ull*)&Q.Lm[jb0 + i - j0] = MUL2(vS[0][i], iv0);
            if (i > j1) *(ull*)&Q.Lm[jb1 + i - j1] = MUL2(vS[1][i], iv1);
        }
    }
    __syncwarp();

    // ---------------- phase 2: trisolve [H | y], y DISTRIBUTED -------------------
    // Lane ql owns H column ql (vH0) and y rows {ql, ql+8} (yw0, yw1).
    ull vH0[16], yw0, yw1;
    #pragma unroll
    for (int m = 0; m < 16; m++) vH0[m] = *(const ull*)&Q.Hy[m][ql];
    yw0 = *(const ull*)&Q.Hy[ql][8];
    yw1 = *(const ull*)&Q.Hy[ql + 8][8];

    #pragma unroll
    for (int k = 0; k < 16; k++) {
        const int cb = k * (33 - k) / 2;
        const int yowner = k & 7;
        // broadcast unscaled yw[k] from its owner lane
        float ykr, yki;
        { ull cur = (k < 8) ? yw0 : yw1; UPK(cur, ykr, yki); }
        ykr = __shfl_sync(FULL, ykr, yowner, 8);
        yki = __shfl_sync(FULL, yki, yowner, 8);
        ull ny = PK(-ykr, -yki), nyb = PK(yki, -ykr);
        float a0, b0_; UPK(vH0[k], a0, b0_);
        ull n0 = PK(-a0, -b0_), n0b = PK(b0_, -a0);
        #pragma unroll
        for (int i = k + 1; i < 16; i++) {
            ull mv = *(const ull*)&Q.Lm[cb + i - k];   // broadcast per batch
            float mr, mi; UPK(mv, mr, mi);
            ull mr2 = PK(mr, mr), mi2 = PK(mi, mi);
            vH0[i] = FMA2(mr2, n0, vH0[i]);
            vH0[i] = FMA2(mi2, n0b, vH0[i]);
            if (i < 8) {
                if (ql == i) { yw0 = FMA2(mr2, ny, yw0); yw0 = FMA2(mi2, nyb, yw0); }
            } else {
                if (ql == i - 8) { yw1 = FMA2(mr2, ny, yw1); yw1 = FMA2(mi2, nyb, yw1); }
            }
        }
        ull ds = *(const ull*)&Q.Lm[cb];                // (rsd, rsd)
        vH0[k] = MUL2(vH0[k], ds);
        if (ql == yowner) {
            if (k < 8) yw0 = MUL2(yw0, ds); else yw1 = MUL2(yw1, ds);
        }
    }
    // lane ql holds whitened column ql (vH0) and whitened y rows ql, ql+8.

    // ---------------- Gram via shfl outer-product (NO smem) ---------------------
    // gcol[i] = g[i][ql] = sum_m conj(Hw[m][i]) * Hw[m][ql];  ymf_ql in-lane.
    ull gcol[8], ymfp = 0ull;
    #pragma unroll
    for (int i = 0; i < 8; i++) gcol[i] = 0ull;
    #pragma unroll
    for (int m = 0; m < 16; m++) {
        float owr, owi; UPK(vH0[m], owr, owi);
        ull own  = vH0[m];
        ull own2 = PK(owi, -owr);
        // broadcast yw[m] from its owner lane
        float yr, yi;
        { ull cur = (m < 8) ? yw0 : yw1; UPK(cur, yr, yi); }
        yr = __shfl_sync(FULL, yr, m & 7, 8);
        yi = __shfl_sync(FULL, yi, m & 7, 8);
        // ymf += conj(own) * yw[m]
        ymfp = FMA2(PK(owr, owr), PK(yr, yi), ymfp);
        ymfp = FMA2(PK(owi, owi), PK(yi, -yr), ymfp);
        #pragma unroll
        for (int t = 0; t < 8; t++) {
            float vr = __shfl_sync(FULL, owr, t, 8);
            float vi = __shfl_sync(FULL, owi, t, 8);
            // gcol[t] += conj(v) * own
            gcol[t] = FMA2(PK(vr, vr), own, gcol[t]);
            gcol[t] = FMA2(PK(vi, vi), own2, gcol[t]);
        }
    }

    // ---------------- MMSE-PIC iterations (quarter-warp, zero smem) -------------
    float l0, l1, l2, l3;
    {
        float4 p = *(const float4*)(prior + (size_t)b * 32 + ql * 4);
        l0 = p.x; l1 = p.y; l2 = p.z; l3 = p.w;
    }
    float ymr, ymi; UPK(ymfp, ymr, ymi);

    float d0 = 0.f, d1 = 0.f, d2 = 0.f, d3 = 0.f;
    float pa0 = 0.f, pa1 = 0.f, pa2 = 0.f, pa3 = 0.f;

    #pragma unroll 1
    for (int iter = 0; iter < 2; iter++) {
        // (a) soft-symbol moments (all 32 lanes useful)
        float s0 = __fdividef(1.f, 1.f + __expf(-l0));
        float s1 = __fdividef(1.f, 1.f + __expf(-l1));
        float s2 = __fdividef(1.f, 1.f + __expf(-l2));
        float s3 = __fdividef(1.f, 1.f + __expf(-l3));
        float mre = (1.f - 2.f * s0) * (1.f + 2.f * s2) * INVS10;
        float mim = (1.f - 2.f * s1) * (1.f + 2.f * s3) * INVS10;
        float var = (2.f + 8.f * (s2 + s3)) * 0.1f - (mre * mre + mim * mim);

        // (b) u_s in-lane via Hermitian symmetry:
        //     u_s = ymf_s - conj( sum_j g[j][s] * conj(x_j) ),  g[j][s] = gcol[j]
        float ur_, ui_;
        {
            ull acc = 0ull;
            #pragma unroll
            for (int j = 0; j < 8; j++) {
                float xrj = __shfl_sync(FULL, mre, j, 8);
                float xij = __shfl_sync(FULL, mim, j, 8);
                float gr, gi; UPK(gcol[j], gr, gi);
                acc = FMA2(PK(xrj, xrj), gcol[j], acc);      // (gr*xr, gi*xr)
                acc = FMA2(PK(xij, xij), PK(gi, -gr), acc);  // (+gi*xi, -gr*xi)
            }
            float ar, ai; UPK(acc, ar, ai);
            ur_ = ymr - ar;          // conj(acc) subtracted
            ui_ = ymi + ai;
        }

        // (c) GJ columns: c2 = g col ql (regs); c1 = c2*var + I; c3 = u on lane 0
        ull c1[8], c2[8], c3[8];
        {
            ull var2 = PK(var, var);
            #pragma unroll
            for (int i = 0; i < 8; i++) {
                c2[i] = gcol[i];
                c1[i] = FMA2(c2[i], var2, PK((i == ql) ? 1.f : 0.f, 0.f));
                c3[i] = 0ull;
            }
            #pragma unroll
            for (int q = 0; q < 8; q++) {
                float tr = __shfl_sync(FULL, ur_, q, 8);
                float ti = __shfl_sync(FULL, ui_, q, 8);
                if (ql == 0) c3[q] = PK(tr, ti);
            }
        }

        // (d) 8x8 complex Gauss-Jordan; width-8 shfl serves all 4 batches
        #pragma unroll
        for (int k = 0; k < 8; k++) {
            float kr, ki; UPK(c1[k], kr, ki);
            float dk = __shfl_sync(FULL, kr, k, 8);   // pivot real
            float invd = __fdividef(1.f, dk);
            ull iv = PK(invd, invd);
            c1[k] = MUL2(c1[k], iv);
            c2[k] = MUL2(c2[k], iv);
            c3[k] = MUL2(c3[k], iv);
            float n1r, n1i; UPK(c1[k], n1r, n1i);
            ull n1 = PK(-n1r, -n1i), n1b = PK(n1i, -n1r);
            float n2r, n2i; UPK(c2[k], n2r, n2i);
            ull n2 = PK(-n2r, -n2i), n2b = PK(n2i, -n2r);
            float n3r, n3i; UPK(c3[k], n3r, n3i);
            ull n3 = PK(-n3r, -n3i), n3b = PK(n3i, -n3r);
            #pragma unroll
            for (int i = 0; i < 8; i++) {
                if (i == k) continue;
                float xr, xi; UPK(c1[i], xr, xi);
                float mr = __shfl_sync(FULL, xr, k, 8);
                float mi = __shfl_sync(FULL, xi, k, 8);
                ull mr2 = PK(mr, mr), mi2 = PK(mi, mi);
                c1[i] = FMA2(mr2, n1, c1[i]);
                c1[i] = FMA2(mi2, n1b, c1[i]);
                c2[i] = FMA2(mr2, n2, c2[i]);
                c2[i] = FMA2(mi2, n2b, c2[i]);
                c3[i] = FMA2(mr2, n3, c3[i]);
                c3[i] = FMA2(mi2, n3b, c3[i]);
            }
        }

        // (e) Mc = (Wg)[ql][ql] lane-local; Wu scattered from lane 0 by shfl
        float Mcr = 0.f, Mci = 0.f;
        #pragma unroll
        for (int q = 0; q < 8; q++)
            if (q == ql) { float a, bq; UPK(c2[q], a, bq); Mcr = a; Mci = bq; }
        float Wur = 0.f, Wui = 0.f;
        #pragma unroll
        for (int q = 0; q < 8; q++) {
            float ar, ai; UPK(c3[q], ar, ai);
            float tr = __shfl_sync(FULL, ar, 0, 8);
            float ti = __shfl_sync(FULL, ai, 0, 8);
            if (ql == q) { Wur = tr; Wui = ti; }
        }

        // (f) finalize + separable max-log demap
        {
            float mu = Mcr;
            float vr = Wur + mre * Mcr - mim * Mci;
            float vi = Wui + mre * Mci + mim * Mcr;
            float invmu = __fdividef(1.f, mu);
            float xr_ = vr * invmu, xi_ = vi * invmu;
            float rho = mu * __fdividef(1.f, fmaxf(1.f - var * mu, EPS_));

            float q1 = rho * 0.1f;
            float c1d = 2.f * INVS10 * rho * xr_;
            float RE00 =        c1d -       q1;
            float RE01 =  3.f * c1d - 9.f * q1 + l2;
            float RE10 =       -c1d -       q1 + l0;
            float RE11 = -3.f * c1d - 9.f * q1 + l0 + l2;
            d0 = fmaxf(RE10, RE11) - fmaxf(RE00, RE01);
            d2 = fmaxf(RE01, RE11) - fmaxf(RE00, RE10);
            float c2d = 2.f * INVS10 * rho * xi_;
            float IM00 =        c2d -       q1;
            float IM01 =  3.f * c2d - 9.f * q1 + l3;
            float IM10 =       -c2d -       q1 + l1;
            float IM11 = -3.f * c2d - 9.f * q1 + l1 + l3;
            d1 = fmaxf(IM10, IM11) - fmaxf(IM00, IM01);
            d3 = fmaxf(IM01, IM11) - fmaxf(IM00, IM10);
        }

        if (iter == 0) {
            pa0 = d0; pa1 = d1; pa2 = d2; pa3 = d3;
            l0 = d0; l1 = d1; l2 = d2; l3 = d3;
        }
    }

    // ---------------- extrinsic output (coalesced float4, all 32 lanes) ---------
    {
        float4 o = make_float4(d0 - pa0, d1 - pa1, d2 - pa2, d3 - pa3);
        *(float4*)(out + (size_t)b * 32 + ql * 4) = o;
    }
}

extern "C" void kernel_launch(void* const* d_in, const int* in_sizes, int n_in,
                              void* d_out, int out_size)
{
    const float* y_re  = (const float*)d_in[0];
    const float* y_im  = (const float*)d_in[1];
    const float* h_re  = (const float*)d_in[2];
    const float* h_im  = (const float*)d_in[3];
    const float* prior = (const float*)d_in[4];
    const float* s_re  = (const float*)d_in[5];
    const float* s_im  = (const float*)d_in[6];
    float* out = (float*)d_out;

    int nbatch = in_sizes[0] / 16;
    int blocks = (nbatch + 15) / 16;    // 16 batches per 128-thread block
    mmse_pic_kernel<<<blocks, 128>>>(y_re, y_im, h_re, h_im, prior,
                                     s_re, s_im, out, nbatch);
}

// round 13
// speedup vs baseline: 1.1910x; 1.1910x over previous
#include <cuda_runtime.h>
#include <math.h>

#define FULL 0xffffffffu
#define INVS10 0.31622776601683794f   // 1/sqrt(10)
#define EPS_ 1e-4f

typedef unsigned long long ull;

__device__ __forceinline__ ull PK(float lo, float hi) {
    ull r; asm("mov.b64 %0, {%1,%2};" : "=l"(r) : "f"(lo), "f"(hi)); return r;
}
__device__ __forceinline__ void UPK(ull v, float& lo, float& hi) {
    asm("mov.b64 {%0,%1}, %2;" : "=f"(lo), "=f"(hi) : "l"(v));
}
__device__ __forceinline__ ull FMA2(ull a, ull b, ull c) {
    ull d; asm("fma.rn.f32x2 %0, %1, %2, %3;" : "=l"(d) : "l"(a), "l"(b), "l"(c)); return d;
}
__device__ __forceinline__ ull MUL2(ull a, ull b) {
    ull d; asm("mul.rn.f32x2 %0, %1, %2;" : "=l"(d) : "l"(a), "l"(b)); return d;
}

// One struct per batch; one QUARTER-warp (8 lanes) owns one batch in all phases.
// Batch stride keeps the 4 simultaneous per-batch LDS broadcasts in distinct banks.
struct __align__(16) BatchSmem {
    float2 Lm[136];          // packed multiplier triangle; diag = (rsd,rsd)
    float2 Hy[16][10];       // staging: H cols 0..7, y col 8
    float2 pad[2];
};

__global__ __launch_bounds__(128)
void mmse_pic_kernel(const float* __restrict__ y_re, const float* __restrict__ y_im,
                     const float* __restrict__ h_re, const float* __restrict__ h_im,
                     const float* __restrict__ prior,
                     const float* __restrict__ s_re, const float* __restrict__ s_im,
                     float* __restrict__ out, int nbatch)
{
    const int warp = threadIdx.x >> 5;
    const int lane = threadIdx.x & 31;
    const int qid  = lane >> 3;        // batch within warp (0..3)
    const int ql   = lane & 7;         // lane within batch
    const int base = blockIdx.x * 16 + warp * 4;

    __shared__ BatchSmem sm[16];
    BatchSmem* SB = &sm[warp * 4];     // this warp's 4 batches
    BatchSmem& Q = SB[qid];

    int b = base + qid; if (b >= nbatch) b = nbatch - 1;

    // ---------------- stage H and y (coalesced) for all 4 batches ----------------
    #pragma unroll
    for (int s2 = 0; s2 < 4; s2++) {
        int bg = base + s2; if (bg >= nbatch) bg = nbatch - 1;
        const float2* hre2 = (const float2*)(h_re + (size_t)bg * 128);
        const float2* him2 = (const float2*)(h_im + (size_t)bg * 128);
        #pragma unroll
        for (int t = lane; t < 64; t += 32) {
            int row = t >> 2, cp = t & 3;
            float2 re = hre2[t], im = him2[t];
            *(float4*)&SB[s2].Hy[row][cp * 2] = make_float4(re.x, im.x, re.y, im.y);
        }
        if (lane < 16)
            SB[s2].Hy[lane][8] = make_float2(y_re[(size_t)bg * 16 + lane],
                                             y_im[(size_t)bg * 16 + lane]);
    }
    __syncwarp();

    // ---------------- load 2 S columns per lane direct from global --------------
    // S Hermitian: column j == conj(row j); rows are contiguous float4 runs.
    ull vS[2][16];
    {
        const float4* sre4 = (const float4*)(s_re + (size_t)b * 256);
        const float4* sim4 = (const float4*)(s_im + (size_t)b * 256);
        #pragma unroll
        for (int c = 0; c < 2; c++) {
            int row = 2 * ql + c;
            #pragma unroll
            for (int q4 = 0; q4 < 4; q4++) {
                float4 r  = sre4[row * 4 + q4];
                float4 i4 = sim4[row * 4 + q4];
                vS[c][4 * q4 + 0] = PK(r.x, -i4.x);
                vS[c][4 * q4 + 1] = PK(r.y, -i4.y);
                vS[c][4 * q4 + 2] = PK(r.z, -i4.z);
                vS[c][4 * q4 + 3] = PK(r.w, -i4.w);
            }
        }
    }

    // ---------------- phase 1: LDL^H elimination of S (8 lanes per batch) -------
    // Column j frozen from step j on -> retains raw multiplier column A[i][j].
    float rsd0 = 0.f, rsd1 = 0.f, invd0 = 0.f, invd1 = 0.f;
    #pragma unroll
    for (int k = 0; k < 16; k++) {
        const int owner = k >> 1, cset = k & 1;
        float pr, pi_; UPK(vS[cset][k], pr, pi_);
        float dk = __shfl_sync(FULL, pr, owner, 8);
        float rsd = rsqrtf(dk);
        float invd = rsd * rsd;
        if (2 * ql == k)     { rsd0 = rsd; invd0 = invd; }
        if (2 * ql + 1 == k) { rsd1 = rsd; invd1 = invd; }
        bool up0 = (2 * ql) > k, up1 = (2 * ql + 1) > k;
        ull nim = PK(-invd, -invd);
        ull w0 = up0 ? MUL2(vS[0][k], nim) : 0ull;      // -invd * A[k][j0]
        ull w1 = up1 ? MUL2(vS[1][k], nim) : 0ull;
        float w0r, w0i; UPK(w0, w0r, w0i); ull w0b = PK(-w0i, w0r);
        float w1r, w1i; UPK(w1, w1r, w1i); ull w1b = PK(-w1i, w1r);
        #pragma unroll
        for (int i = k + 1; i < 16; i++) {
            float xr, xi; UPK(vS[cset][i], xr, xi);
            float mr = __shfl_sync(FULL, xr, owner, 8);   // A[i][k] raw
            float mi = __shfl_sync(FULL, xi, owner, 8);
            ull mr2 = PK(mr, mr), mi2 = PK(mi, mi);
            vS[0][i] = FMA2(mr2, w0, vS[0][i]);
            vS[0][i] = FMA2(mi2, w0b, vS[0][i]);
            vS[1][i] = FMA2(mr2, w1, vS[1][i]);
            vS[1][i] = FMA2(mi2, w1b, vS[1][i]);
        }
    }
    // store scaled multiplier columns (packed triangle) + diag rsd
    {
        int j0 = 2 * ql, j1 = 2 * ql + 1;
        int jb0 = j0 * (33 - j0) / 2, jb1 = j1 * (33 - j1) / 2;
        *(ull*)&Q.Lm[jb0] = PK(rsd0, rsd0);
        *(ull*)&Q.Lm[jb1] = PK(rsd1, rsd1);
        ull iv0 = PK(invd0, invd0), iv1 = PK(invd1, invd1);
        #pragma unroll
        for (int i = 1; i < 16; i++) {
            if (i > j0) *(ull*)&Q.Lm[jb0 + i - j0] = MUL2(vS[0][i], iv0);
            if (i > j1) *(ull*)&Q.Lm[jb1 + i - j1] = MUL2(vS[1][i], iv1);
        }
    }
    __syncwarp();

    // ---------------- phase 2: trisolve [H | y] (y replicated per lane) ---------
    ull vH[2][16];
    #pragma unroll
    for (int m = 0; m < 16; m++) {
        vH[0][m] = *(const ull*)&Q.Hy[m][ql];
        vH[1][m] = *(const ull*)&Q.Hy[m][8];
    }
    #pragma unroll
    for (int k = 0; k < 16; k++) {
        const int cb = k * (33 - k) / 2;
        float a0, b0_; UPK(vH[0][k], a0, b0_);
        ull n0 = PK(-a0, -b0_), n0b = PK(b0_, -a0);
        float a1, b1_; UPK(vH[1][k], a1, b1_);
        ull n1 = PK(-a1, -b1_), n1b = PK(b1_, -a1);
        #pragma unroll
        for (int i = k + 1; i < 16; i++) {
            ull mv = *(const ull*)&Q.Lm[cb + i - k];   // broadcast per batch
            float mr, mi; UPK(mv, mr, mi);
            ull mr2 = PK(mr, mr), mi2 = PK(mi, mi);
            vH[0][i] = FMA2(mr2, n0, vH[0][i]);
            vH[0][i] = FMA2(mi2, n0b, vH[0][i]);
            vH[1][i] = FMA2(mr2, n1, vH[1][i]);
            vH[1][i] = FMA2(mi2, n1b, vH[1][i]);
        }
        ull ds = *(const ull*)&Q.Lm[cb];                // (rsd, rsd)
        vH[0][k] = MUL2(vH[0][k], ds);
        vH[1][k] = MUL2(vH[1][k], ds);
    }
    // lane ql now holds whitened column ql in vH[0], whitened y in vH[1].

    // ---------------- Gram via shfl outer-product (NO smem) ---------------------
    // gcol[i] = g[i][ql] = sum_m conj(Hw[m][i]) * Hw[m][ql];  ymf_ql in-lane.
    ull gcol[8], ymfp = 0ull;
    #pragma unroll
    for (int i = 0; i < 8; i++) gcol[i] = 0ull;
    #pragma unroll
    for (int m = 0; m < 16; m++) {
        float owr, owi; UPK(vH[0][m], owr, owi);
        ull own  = vH[0][m];
        ull own2 = PK(owi, -owr);
        // ymf += conj(own) * yw
        float yr, yi; UPK(vH[1][m], yr, yi);
        ymfp = FMA2(PK(owr, owr), vH[1][m], ymfp);     // (or*yr, or*yi)
        ymfp = FMA2(PK(owi, owi), PK(yi, -yr), ymfp);  // (+oi*yi, -oi*yr)
        #pragma unroll
        for (int t = 0; t < 8; t++) {
            float vr = __shfl_sync(FULL, owr, t, 8);
            float vi = __shfl_sync(FULL, owi, t, 8);
            // gcol[t] += conj(v) * own = (vr*or + vi*oi, vr*oi - vi*or)
            gcol[t] = FMA2(PK(vr, vr), own, gcol[t]);
            gcol[t] = FMA2(PK(vi, vi), own2, gcol[t]);
        }
    }

    // ---------------- MMSE-PIC iterations (quarter-warp, zero smem) -------------
    float l0, l1, l2, l3;
    {
        float4 p = *(const float4*)(prior + (size_t)b * 32 + ql * 4);
        l0 = p.x; l1 = p.y; l2 = p.z; l3 = p.w;
    }
    float ymr, ymi; UPK(ymfp, ymr, ymi);

    float d0 = 0.f, d1 = 0.f, d2 = 0.f, d3 = 0.f;
    float pa0 = 0.f, pa1 = 0.f, pa2 = 0.f, pa3 = 0.f;

    #pragma unroll 1
    for (int iter = 0; iter < 2; iter++) {
        // (a) soft-symbol moments (all 32 lanes useful)
        float s0 = __fdividef(1.f, 1.f + __expf(-l0));
        float s1 = __fdividef(1.f, 1.f + __expf(-l1));
        float s2 = __fdividef(1.f, 1.f + __expf(-l2));
        float s3 = __fdividef(1.f, 1.f + __expf(-l3));
        float mre = (1.f - 2.f * s0) * (1.f + 2.f * s2) * INVS10;
        float mim = (1.f - 2.f * s1) * (1.f + 2.f * s3) * INVS10;
        float var = (2.f + 8.f * (s2 + s3)) * 0.1f - (mre * mre + mim * mim);

        // (b) u_s in-lane via Hermitian symmetry:
        //     u_s = ymf_s - conj( sum_j g[j][s] * conj(x_j) ),  g[j][s] = gcol[j]
        float ur_, ui_;
        {
            ull acc = 0ull;
            #pragma unroll
            for (int j = 0; j < 8; j++) {
                float xrj = __shfl_sync(FULL, mre, j, 8);
                float xij = __shfl_sync(FULL, mim, j, 8);
                float gr, gi; UPK(gcol[j], gr, gi);
                acc = FMA2(PK(xrj, xrj), gcol[j], acc);      // (gr*xr, gi*xr)
                acc = FMA2(PK(xij, xij), PK(gi, -gr), acc);  // (+gi*xi, -gr*xi)
            }
            float ar, ai; UPK(acc, ar, ai);
            ur_ = ymr - ar;          // conj(acc) subtracted
            ui_ = ymi + ai;
        }
        // t = var * u  (lane-local; broadcast later for the Wu identity)
        float tr_ = var * ur_, ti_ = var * ui_;

        // (c) GJ columns: c2 = g col ql (regs); c1 = a_c col = c2*var + I
        ull c1[8], c2[8];
        {
            ull var2 = PK(var, var);
            #pragma unroll
            for (int i = 0; i < 8; i++) {
                c2[i] = gcol[i];
                c1[i] = FMA2(c2[i], var2, PK((i == ql) ? 1.f : 0.f, 0.f));
            }
        }

        // (d) 8x8 complex Gauss-Jordan (c1, c2 only); width-8 shfl serves 4 batches
        #pragma unroll
        for (int k = 0; k < 8; k++) {
            float kr, ki; UPK(c1[k], kr, ki);
            float dk = __shfl_sync(FULL, kr, k, 8);   // pivot real
            float invd = __fdividef(1.f, dk);
            ull iv = PK(invd, invd);
            c1[k] = MUL2(c1[k], iv);
            c2[k] = MUL2(c2[k], iv);
            float n1r, n1i; UPK(c1[k], n1r, n1i);
            ull n1 = PK(-n1r, -n1i), n1b = PK(n1i, -n1r);
            float n2r, n2i; UPK(c2[k], n2r, n2i);
            ull n2 = PK(-n2r, -n2i), n2b = PK(n2i, -n2r);
            #pragma unroll
            for (int i = 0; i < 8; i++) {
                if (i == k) continue;
                float xr, xi; UPK(c1[i], xr, xi);
                float mr = __shfl_sync(FULL, xr, k, 8);
                float mi = __shfl_sync(FULL, xi, k, 8);
                ull mr2 = PK(mr, mr), mi2 = PK(mi, mi);
                c1[i] = FMA2(mr2, n1, c1[i]);
                c1[i] = FMA2(mi2, n1b, c1[i]);
                c2[i] = FMA2(mr2, n2, c2[i]);
                c2[i] = FMA2(mi2, n2b, c2[i]);
            }
        }
        // c2 is now column ql of Wg = (I + gV)^{-1} g,  which is HERMITIAN.

        // (e) Mc = (Wg)[ql][ql] lane-local.
        //     Wu via identity W = I - (Wg)V:
        //     Wu_ql = u_ql - sum_j (Wg)[ql][j] t_j = u_ql - sum_j conj(c2[j]) t_j
        float Mcr = 0.f, Mci = 0.f;
        #pragma unroll
        for (int q = 0; q < 8; q++)
            if (q == ql) { float a, bq; UPK(c2[q], a, bq); Mcr = a; Mci = bq; }
        float Wur, Wui;
        {
            ull acc = 0ull;
            #pragma unroll
            for (int j = 0; j < 8; j++) {
                float tjr = __shfl_sync(FULL, tr_, j, 8);
                float tji = __shfl_sync(FULL, ti_, j, 8);
                float gr, gi; UPK(c2[j], gr, gi);
                // conj(c2[j]) * t = (gr*tr + gi*ti, gr*ti - gi*tr)
                acc = FMA2(PK(tjr, tjr), PK(gr, -gi), acc);
                acc = FMA2(PK(tji, tji), PK(gi, gr), acc);
            }
            float ar, ai; UPK(acc, ar, ai);
            Wur = ur_ - ar;
            Wui = ui_ - ai;
        }

        // (f) finalize + separable max-log demap
        {
            float mu = Mcr;
            float vr = Wur + mre * Mcr - mim * Mci;
            float vi = Wui + mre * Mci + mim * Mcr;
            float invmu = __fdividef(1.f, mu);
            float xr_ = vr * invmu, xi_ = vi * invmu;
            float rho = mu * __fdividef(1.f, fmaxf(1.f - var * mu, EPS_));

            float q1 = rho * 0.1f;
            float c1d = 2.f * INVS10 * rho * xr_;
            float RE00 =        c1d -       q1;
            float RE01 =  3.f * c1d - 9.f * q1 + l2;
            float RE10 =       -c1d -       q1 + l0;
            float RE11 = -3.f * c1d - 9.f * q1 + l0 + l2;
            d0 = fmaxf(RE10, RE11) - fmaxf(RE00, RE01);
            d2 = fmaxf(RE01, RE11) - fmaxf(RE00, RE10);
            float c2d = 2.f * INVS10 * rho * xi_;
            float IM00 =        c2d -       q1;
            float IM01 =  3.f * c2d - 9.f * q1 + l3;
            float IM10 =       -c2d -       q1 + l1;
            float IM11 = -3.f * c2d - 9.f * q1 + l1 + l3;
            d1 = fmaxf(IM10, IM11) - fmaxf(IM00, IM01);
            d3 = fmaxf(IM01, IM11) - fmaxf(IM00, IM10);
        }

        if (iter == 0) {
            pa0 = d0; pa1 = d1; pa2 = d2; pa3 = d3;
            l0 = d0; l1 = d1; l2 = d2; l3 = d3;
        }
    }

    // ---------------- extrinsic output (coalesced float4, all 32 lanes) ---------
    {
        float4 o = make_float4(d0 - pa0, d1 - pa1, d2 - pa2, d3 - pa3);
        *(float4*)(out + (size_t)b * 32 + ql * 4) = o;
    }
}

extern "C" void kernel_launch(void* const* d_in, const int* in_sizes, int n_in,
                              void* d_out, int out_size)
{
    const float* y_re  = (const float*)d_in[0];
    const float* y_im  = (const float*)d_in[1];
    const float* h_re  = (const float*)d_in[2];
    const float* h_im  = (const float*)d_in[3];
    const float* prior = (const float*)d_in[4];
    const float* s_re  = (const float*)d_in[5];
    const float* s_im  = (const float*)d_in[6];
    float* out = (float*)d_out;

    int nbatch = in_sizes[0] / 16;
    int blocks = (nbatch + 15) / 16;    // 16 batches per 128-thread block
    mmse_pic_kernel<<<blocks, 128>>>(y_re, y_im, h_re, h_im, prior,
                                     s_re, s_im, out, nbatch);
}